// round 2
// baseline (speedup 1.0000x reference)
#include <cuda_runtime.h>
#include <cuda_bf16.h>

// Problem constants (fixed by setup_inputs)
#define NN  1024   // n
#define RAW 128
#define DD  128    // latent d
#define HH  256    // hidden h

#define SELU_ALPHA 1.6732632423543772f
#define SELU_SCALE 1.0507009873554805f

// Scratch (static __device__ arrays; no allocation)
__device__ float g_z  [NN * DD];       // z = x@W_enc + b_enc          [j][c]
__device__ float g_AT [HH * NN];       // A^T (incl. b1)               [k][j]
__device__ float g_EAT[HH * NN];       // exp(A^T)                     [k][j]
__device__ float g_BT [HH * NN];       // B^T                          [k][i]
__device__ float g_EBT[HH * NN];       // exp(B^T)                     [k][i]
__device__ float g_sw [HH];            // scale * W2
__device__ float g_c0;                 // b2 - alpha*scale*sum(W2)

// ---------------------------------------------------------------------------
// prep: sw[k] = scale*W2[k]; c0 = b2 - alpha*scale*sum(W2)
// ---------------------------------------------------------------------------
__global__ void prep_kernel(const float* __restrict__ W2,
                            const float* __restrict__ b2) {
    __shared__ float red[HH];
    int t = threadIdx.x;
    float w = W2[t];
    g_sw[t] = SELU_SCALE * w;
    red[t] = w;
    __syncthreads();
    #pragma unroll
    for (int s = HH / 2; s > 0; s >>= 1) {
        if (t < s) red[t] += red[t + s];
        __syncthreads();
    }
    if (t == 0) g_c0 = b2[0] - SELU_ALPHA * SELU_SCALE * red[0];
}

// ---------------------------------------------------------------------------
// z = x @ W_enc + b_enc.  128 blocks x 128 threads; 8 rows per block.
// ---------------------------------------------------------------------------
__global__ void z_kernel(const float* __restrict__ x,
                         const float* __restrict__ W_enc,
                         const float* __restrict__ b_enc) {
    __shared__ float sx[8][RAW];
    const int t  = threadIdx.x;      // output column k in [0,128)
    const int j0 = blockIdx.x * 8;

    #pragma unroll
    for (int r = 0; r < 8; r++)
        sx[r][t] = x[(j0 + r) * RAW + t];
    __syncthreads();

    float acc[8];
    #pragma unroll
    for (int r = 0; r < 8; r++) acc[r] = 0.0f;

    for (int c = 0; c < RAW; c++) {
        float w = W_enc[c * DD + t];
        #pragma unroll
        for (int r = 0; r < 8; r++)
            acc[r] = fmaf(sx[r][c], w, acc[r]);
    }
    float bb = b_enc[t];
    #pragma unroll
    for (int r = 0; r < 8; r++)
        g_z[(j0 + r) * DD + t] = acc[r] + bb;
}

// ---------------------------------------------------------------------------
// A^T = (z @ W1[:d] + b1)^T ; B^T = (z @ W1[d:])^T ; plus exp() of both.
// 128 blocks x 256 threads; 8 j-rows per block, thread t = column k.
// ---------------------------------------------------------------------------
__global__ void ab_kernel(const float* __restrict__ W1,
                          const float* __restrict__ b1) {
    __shared__ float sz[8 * DD];
    const int t  = threadIdx.x;      // k in [0,256)
    const int j0 = blockIdx.x * 8;

    for (int idx = t; idx < 8 * DD; idx += 256)
        sz[idx] = g_z[j0 * DD + idx];
    __syncthreads();

    float accA[8], accB[8];
    #pragma unroll
    for (int r = 0; r < 8; r++) { accA[r] = 0.0f; accB[r] = 0.0f; }

    for (int c = 0; c < DD; c++) {
        float wa = W1[c * HH + t];
        float wb = W1[(c + DD) * HH + t];
        #pragma unroll
        for (int r = 0; r < 8; r++) {
            float zz = sz[r * DD + c];
            accA[r] = fmaf(zz, wa, accA[r]);
            accB[r] = fmaf(zz, wb, accB[r]);
        }
    }
    float b1k = b1[t];
    #pragma unroll
    for (int r = 0; r < 8; r++) {
        int j = j0 + r;
        float a = accA[r] + b1k;
        float b = accB[r];
        g_AT [t * NN + j] = a;
        g_BT [t * NN + j] = b;
        g_EAT[t * NN + j] = __expf(fminf(fmaxf(a, -60.0f), 60.0f));
        g_EBT[t * NN + j] = __expf(fminf(fmaxf(b, -60.0f), 60.0f));
    }
}

// ---------------------------------------------------------------------------
// Main: o[i,j] = hard_sigmoid( sum_k (max(v,0) + alpha*min(e,1)) * sw[k] + c0 )
//   v = AT[k][j] + BT[k][i],  e = EAT[k][j] * EBT[k][i]  (== exp(v))
// Grid (16,16): 64x64 tiles. Block (16,16): 4x4 per thread. KC=16 k-chunks.
// ---------------------------------------------------------------------------
__global__ __launch_bounds__(256) void main_kernel(float* __restrict__ out) {
    __shared__ float4 s_a [16][16];
    __shared__ float4 s_ea[16][16];
    __shared__ float4 s_b [16][16];
    __shared__ float4 s_eb[16][16];
    __shared__ float  ssw[16];

    const int tx  = threadIdx.x;            // j sub-tile
    const int ty  = threadIdx.y;            // i sub-tile
    const int tid = ty * 16 + tx;
    const int j0  = blockIdx.x * 64;
    const int i0  = blockIdx.y * 64;

    const float4* AT4  = reinterpret_cast<const float4*>(g_AT);
    const float4* EAT4 = reinterpret_cast<const float4*>(g_EAT);
    const float4* BT4  = reinterpret_cast<const float4*>(g_BT);
    const float4* EBT4 = reinterpret_cast<const float4*>(g_EBT);

    float acc[4][4];
    #pragma unroll
    for (int ii = 0; ii < 4; ii++)
        #pragma unroll
        for (int jj = 0; jj < 4; jj++)
            acc[ii][jj] = 0.0f;

    const int kk_ld = tid >> 4;   // 0..15 : k row within chunk
    const int c4_ld = tid & 15;   // 0..15 : float4 column within 64-wide window

    for (int k0 = 0; k0 < HH; k0 += 16) {
        __syncthreads();
        {
            int ga = (k0 + kk_ld) * (NN / 4) + (j0 >> 2) + c4_ld;
            int gb = (k0 + kk_ld) * (NN / 4) + (i0 >> 2) + c4_ld;
            s_a [kk_ld][c4_ld] = AT4 [ga];
            s_ea[kk_ld][c4_ld] = EAT4[ga];
            s_b [kk_ld][c4_ld] = BT4 [gb];
            s_eb[kk_ld][c4_ld] = EBT4[gb];
            if (tid < 16) ssw[tid] = g_sw[k0 + tid];
        }
        __syncthreads();

        #pragma unroll
        for (int kk = 0; kk < 16; kk++) {
            float4 a  = s_a [kk][tx];
            float4 ea = s_ea[kk][tx];
            float4 b  = s_b [kk][ty];
            float4 eb = s_eb[kk][ty];
            float  w  = ssw[kk];

            float av[4]  = {a.x,  a.y,  a.z,  a.w};
            float eav[4] = {ea.x, ea.y, ea.z, ea.w};
            float bv[4]  = {b.x,  b.y,  b.z,  b.w};
            float ebv[4] = {eb.x, eb.y, eb.z, eb.w};

            #pragma unroll
            for (int ii = 0; ii < 4; ii++) {
                #pragma unroll
                for (int jj = 0; jj < 4; jj++) {
                    float v = av[jj] + bv[ii];
                    float e = eav[jj] * ebv[ii];
                    float t = fmaf(SELU_ALPHA, fminf(e, 1.0f), fmaxf(v, 0.0f));
                    acc[ii][jj] = fmaf(t, w, acc[ii][jj]);
                }
            }
        }
    }

    const float c0 = g_c0;
    #pragma unroll
    for (int ii = 0; ii < 4; ii++) {
        int i = i0 + ty * 4 + ii;
        float4 o;
        float r0 = acc[ii][0] + c0;
        float r1 = acc[ii][1] + c0;
        float r2 = acc[ii][2] + c0;
        float r3 = acc[ii][3] + c0;
        o.x = fminf(fmaxf(r0 + 3.0f, 0.0f), 6.0f) * (1.0f / 6.0f);
        o.y = fminf(fmaxf(r1 + 3.0f, 0.0f), 6.0f) * (1.0f / 6.0f);
        o.z = fminf(fmaxf(r2 + 3.0f, 0.0f), 6.0f) * (1.0f / 6.0f);
        o.w = fminf(fmaxf(r3 + 3.0f, 0.0f), 6.0f) * (1.0f / 6.0f);
        *reinterpret_cast<float4*>(&out[i * NN + j0 + tx * 4]) = o;
    }
}

// ---------------------------------------------------------------------------
extern "C" void kernel_launch(void* const* d_in, const int* in_sizes, int n_in,
                              void* d_out, int out_size) {
    const float* x     = (const float*)d_in[0];
    const float* W_enc = (const float*)d_in[1];
    const float* b_enc = (const float*)d_in[2];
    const float* W1    = (const float*)d_in[3];
    const float* b1    = (const float*)d_in[4];
    const float* W2    = (const float*)d_in[5];
    const float* b2    = (const float*)d_in[6];
    float* out = (float*)d_out;

    prep_kernel<<<1, HH>>>(W2, b2);
    z_kernel<<<NN / 8, 128>>>(x, W_enc, b_enc);
    ab_kernel<<<NN / 8, 256>>>(W1, b1);

    dim3 grid(NN / 64, NN / 64);
    dim3 block(16, 16);
    main_kernel<<<grid, block>>>(out);
}

// round 3
// speedup vs baseline: 1.3584x; 1.3584x over previous
#include <cuda_runtime.h>
#include <cuda_bf16.h>

// Problem constants (fixed by setup_inputs)
#define NN  1024   // n
#define RAW 128
#define DD  128    // latent d
#define HH  256    // hidden h

#define SELU_ALPHA 1.6732632423543772f
#define SELU_SCALE 1.0507009873554805f

typedef unsigned long long ull;

// Packed f32x2 helpers (Blackwell sm_103a)
#define ADD2(d, a, b)    asm("add.rn.f32x2 %0, %1, %2;" : "=l"(d) : "l"(a), "l"(b))
#define FMA2(d, a, b, c) asm("fma.rn.f32x2 %0, %1, %2, %3;" : "=l"(d) : "l"(a), "l"(b), "l"(c))
#define PACK2(d, lo, hi) asm("mov.b64 %0, {%1, %2};" : "=l"(d) : "f"(lo), "f"(hi))
#define UNPACK2(lo, hi, s) asm("mov.b64 {%0, %1}, %2;" : "=f"(lo), "=f"(hi) : "l"(s))
#define MULSAT(d, a, b)  asm("mul.rn.sat.f32 %0, %1, %2;" : "=f"(d) : "f"(a), "f"(b))

// Scratch (static __device__ arrays; no allocation)
__device__ float g_z  [NN * DD];       // z = x@W_enc + b_enc          [j][c]
__device__ float g_AT [HH * NN];       // A^T (incl. b1)               [k][j]
__device__ float g_EAT[HH * NN];       // exp(A^T)                     [k][j]
__device__ float g_BT [HH * NN];       // B^T                          [k][i]
__device__ float g_EBT[HH * NN];       // exp(B^T)                     [k][i]
__device__ float g_sw [HH];            // scale * W2
__device__ float g_asw[HH];            // alpha * scale * W2
__device__ float g_c0;                 // b2 - alpha*scale*sum(W2)

// ---------------------------------------------------------------------------
// prep: sw[k] = scale*W2[k]; asw[k] = alpha*scale*W2[k];
//       c0 = b2 - alpha*scale*sum(W2)
// ---------------------------------------------------------------------------
__global__ void prep_kernel(const float* __restrict__ W2,
                            const float* __restrict__ b2) {
    __shared__ float red[HH];
    int t = threadIdx.x;
    float w = W2[t];
    g_sw[t]  = SELU_SCALE * w;
    g_asw[t] = SELU_ALPHA * SELU_SCALE * w;
    red[t] = w;
    __syncthreads();
    #pragma unroll
    for (int s = HH / 2; s > 0; s >>= 1) {
        if (t < s) red[t] += red[t + s];
        __syncthreads();
    }
    if (t == 0) g_c0 = b2[0] - SELU_ALPHA * SELU_SCALE * red[0];
}

// ---------------------------------------------------------------------------
// z = x @ W_enc + b_enc.  128 blocks x 128 threads; 8 rows per block.
// ---------------------------------------------------------------------------
__global__ void z_kernel(const float* __restrict__ x,
                         const float* __restrict__ W_enc,
                         const float* __restrict__ b_enc) {
    __shared__ float sx[8][RAW];
    const int t  = threadIdx.x;      // output column k in [0,128)
    const int j0 = blockIdx.x * 8;

    #pragma unroll
    for (int r = 0; r < 8; r++)
        sx[r][t] = x[(j0 + r) * RAW + t];
    __syncthreads();

    float acc[8];
    #pragma unroll
    for (int r = 0; r < 8; r++) acc[r] = 0.0f;

    for (int c = 0; c < RAW; c++) {
        float w = W_enc[c * DD + t];
        #pragma unroll
        for (int r = 0; r < 8; r++)
            acc[r] = fmaf(sx[r][c], w, acc[r]);
    }
    float bb = b_enc[t];
    #pragma unroll
    for (int r = 0; r < 8; r++)
        g_z[(j0 + r) * DD + t] = acc[r] + bb;
}

// ---------------------------------------------------------------------------
// A^T = (z @ W1[:d] + b1)^T ; B^T = (z @ W1[d:])^T ; plus exp() of both.
// 128 blocks x 256 threads; 8 j-rows per block, thread t = column k.
// Writes go through a shared-memory transpose so each warp stores
// sector-aligned 32B runs instead of stride-4KB scatters.
// ---------------------------------------------------------------------------
__global__ void ab_kernel(const float* __restrict__ W1,
                          const float* __restrict__ b1) {
    __shared__ float sz[8 * DD];
    __shared__ float stV[HH * 9];   // value,  padded rows (9) vs bank conflicts
    __shared__ float stE[HH * 9];   // exp(value)
    const int t  = threadIdx.x;      // k in [0,256)
    const int j0 = blockIdx.x * 8;

    for (int idx = t; idx < 8 * DD; idx += 256)
        sz[idx] = g_z[j0 * DD + idx];
    __syncthreads();

    float accA[8], accB[8];
    #pragma unroll
    for (int r = 0; r < 8; r++) { accA[r] = 0.0f; accB[r] = 0.0f; }

    for (int c = 0; c < DD; c++) {
        float wa = W1[c * HH + t];
        float wb = W1[(c + DD) * HH + t];
        #pragma unroll
        for (int r = 0; r < 8; r++) {
            float zz = sz[r * DD + c];
            accA[r] = fmaf(zz, wa, accA[r]);
            accB[r] = fmaf(zz, wb, accB[r]);
        }
    }
    float b1k = b1[t];

    const int kx = t >> 3;   // 0..31 : k row within pass
    const int jt = t & 7;    // 0..7  : j within block tile

    // ---- round 1: A and exp(A) ----
    #pragma unroll
    for (int r = 0; r < 8; r++) {
        float a = accA[r] + b1k;
        stV[t * 9 + r] = a;
        stE[t * 9 + r] = __expf(fminf(fmaxf(a, -60.0f), 60.0f));
    }
    __syncthreads();
    #pragma unroll
    for (int p = 0; p < 8; p++) {
        int k = p * 32 + kx;
        g_AT [k * NN + j0 + jt] = stV[k * 9 + jt];
        g_EAT[k * NN + j0 + jt] = stE[k * 9 + jt];
    }
    __syncthreads();

    // ---- round 2: B and exp(B) ----
    #pragma unroll
    for (int r = 0; r < 8; r++) {
        float b = accB[r];
        stV[t * 9 + r] = b;
        stE[t * 9 + r] = __expf(fminf(fmaxf(b, -60.0f), 60.0f));
    }
    __syncthreads();
    #pragma unroll
    for (int p = 0; p < 8; p++) {
        int k = p * 32 + kx;
        g_BT [k * NN + j0 + jt] = stV[k * 9 + jt];
        g_EBT[k * NN + j0 + jt] = stE[k * 9 + jt];
    }
}

// ---------------------------------------------------------------------------
// Main: o[i,j] = hard_sigmoid( sum_k [ sw[k]*max(v,0) + asw[k]*sat(e) ] + c0 )
//   v = AT[k][j] + BT[k][i],  e = EAT[k][j] * EBT[k][i]  (== exp(v) >= 0,
//   so sat(e) == min(e,1)).
// Packed f32x2 over j-pairs: ADD2 for v, FMUL.SAT for e, FMNMX for relu,
// two FFMA2 into packed accumulators.
// Grid (16,16): 64x64 tiles. Block (16,16): 4x4 per thread. KC=16 chunks,
// next chunk prefetched into registers while current computes.
// ---------------------------------------------------------------------------
__global__ __launch_bounds__(256, 2) void main_kernel(float* __restrict__ out) {
    __shared__ float4 s_a [16][16];
    __shared__ float4 s_ea[16][16];
    __shared__ float4 s_b [16][16];
    __shared__ float4 s_eb[16][16];
    __shared__ float  s_w [16];
    __shared__ float  s_aw[16];

    const int tx  = threadIdx.x;            // j sub-tile
    const int ty  = threadIdx.y;            // i sub-tile
    const int tid = ty * 16 + tx;
    const int j0  = blockIdx.x * 64;
    const int i0  = blockIdx.y * 64;

    const float4* AT4  = reinterpret_cast<const float4*>(g_AT);
    const float4* EAT4 = reinterpret_cast<const float4*>(g_EAT);
    const float4* BT4  = reinterpret_cast<const float4*>(g_BT);
    const float4* EBT4 = reinterpret_cast<const float4*>(g_EBT);

    ull acc[4][2];
    #pragma unroll
    for (int i = 0; i < 4; i++) {
        acc[i][0] = 0ull;
        acc[i][1] = 0ull;
    }

    const int kk_ld = tid >> 4;   // 0..15 : k row within chunk
    const int c4_ld = tid & 15;   // 0..15 : float4 column within 64-wide window

    // register prefetch of chunk data
    float4 ra, rea, rb, reb;
    float  rw = 0.0f, raw_ = 0.0f;
    {
        int ga = kk_ld * (NN / 4) + (j0 >> 2) + c4_ld;
        int gb = kk_ld * (NN / 4) + (i0 >> 2) + c4_ld;
        ra  = AT4 [ga];
        rea = EAT4[ga];
        rb  = BT4 [gb];
        reb = EBT4[gb];
        if (tid < 16)       rw   = g_sw [tid];
        else if (tid < 32)  raw_ = g_asw[tid - 16];
    }

    for (int c = 0; c < 16; c++) {
        __syncthreads();
        s_a [kk_ld][c4_ld] = ra;
        s_ea[kk_ld][c4_ld] = rea;
        s_b [kk_ld][c4_ld] = rb;
        s_eb[kk_ld][c4_ld] = reb;
        if (tid < 16)      s_w [tid]      = rw;
        else if (tid < 32) s_aw[tid - 16] = raw_;
        __syncthreads();

        if (c < 15) {
            int k0 = (c + 1) * 16;
            int ga = (k0 + kk_ld) * (NN / 4) + (j0 >> 2) + c4_ld;
            int gb = (k0 + kk_ld) * (NN / 4) + (i0 >> 2) + c4_ld;
            ra  = AT4 [ga];
            rea = EAT4[ga];
            rb  = BT4 [gb];
            reb = EBT4[gb];
            if (tid < 16)      rw   = g_sw [k0 + tid];
            else if (tid < 32) raw_ = g_asw[k0 + tid - 16];
        }

        #pragma unroll
        for (int kk = 0; kk < 16; kk++) {
            ulonglong2 a2v = *reinterpret_cast<const ulonglong2*>(&s_a[kk][tx]);
            float4 ea  = s_ea[kk][tx];
            float4 b4  = s_b [kk][ty];
            float4 eb4 = s_eb[kk][ty];
            float  w   = s_w [kk];
            float  aw  = s_aw[kk];

            ull w2, aw2;
            PACK2(w2,  w,  w);
            PACK2(aw2, aw, aw);

            ull   a2p[2] = {a2v.x, a2v.y};
            float eav[4] = {ea.x, ea.y, ea.z, ea.w};
            float bv [4] = {b4.x, b4.y, b4.z, b4.w};
            float ebv[4] = {eb4.x, eb4.y, eb4.z, eb4.w};

            #pragma unroll
            for (int i = 0; i < 4; i++) {
                ull b2;
                PACK2(b2, bv[i], bv[i]);
                float ebi = ebv[i];
                #pragma unroll
                for (int jp = 0; jp < 2; jp++) {
                    ull v2;
                    ADD2(v2, a2p[jp], b2);
                    float vl, vh;
                    UNPACK2(vl, vh, v2);
                    float e0, e1;
                    MULSAT(e0, eav[2 * jp],     ebi);
                    MULSAT(e1, eav[2 * jp + 1], ebi);
                    float r0 = fmaxf(vl, 0.0f);
                    float r1 = fmaxf(vh, 0.0f);
                    ull e2, r2;
                    PACK2(e2, e0, e1);
                    PACK2(r2, r0, r1);
                    FMA2(acc[i][jp], e2, aw2, acc[i][jp]);
                    FMA2(acc[i][jp], r2, w2,  acc[i][jp]);
                }
            }
        }
    }

    const float c0 = g_c0;
    #pragma unroll
    for (int ii = 0; ii < 4; ii++) {
        int i = i0 + ty * 4 + ii;
        float a0, a1, a2, a3;
        UNPACK2(a0, a1, acc[ii][0]);
        UNPACK2(a2, a3, acc[ii][1]);
        float4 o;
        o.x = fminf(fmaxf(a0 + c0 + 3.0f, 0.0f), 6.0f) * (1.0f / 6.0f);
        o.y = fminf(fmaxf(a1 + c0 + 3.0f, 0.0f), 6.0f) * (1.0f / 6.0f);
        o.z = fminf(fmaxf(a2 + c0 + 3.0f, 0.0f), 6.0f) * (1.0f / 6.0f);
        o.w = fminf(fmaxf(a3 + c0 + 3.0f, 0.0f), 6.0f) * (1.0f / 6.0f);
        *reinterpret_cast<float4*>(&out[i * NN + j0 + tx * 4]) = o;
    }
}

// ---------------------------------------------------------------------------
extern "C" void kernel_launch(void* const* d_in, const int* in_sizes, int n_in,
                              void* d_out, int out_size) {
    const float* x     = (const float*)d_in[0];
    const float* W_enc = (const float*)d_in[1];
    const float* b_enc = (const float*)d_in[2];
    const float* W1    = (const float*)d_in[3];
    const float* b1    = (const float*)d_in[4];
    const float* W2    = (const float*)d_in[5];
    const float* b2    = (const float*)d_in[6];
    float* out = (float*)d_out;

    prep_kernel<<<1, HH>>>(W2, b2);
    z_kernel<<<NN / 8, 128>>>(x, W_enc, b_enc);
    ab_kernel<<<NN / 8, 256>>>(W1, b1);

    dim3 grid(NN / 64, NN / 64);
    dim3 block(16, 16);
    main_kernel<<<grid, block>>>(out);
}